// round 11
// baseline (speedup 1.0000x reference)
#include <cuda_runtime.h>
#include <cuda_bf16.h>

// ---------------------------------------------------------------------------
// AdaptiveRankingLoss R11: alu-stream diet via operand modifiers + predicate
// fusion. Structure frozen at R10 (best measured: 26.1us).
//   loss = mean over valid pairs (|t_i-t_j| >= 0.05, i<j) of
//          0.5*(s_i+s_j)*relu(-sign(t_i-t_j)*(p_i-p_j) + 0.08*ms*clip(ad,0.1,1))
// Changes vs R10 (per pair):
//   - |td| consumed only as operand modifier (FMNMX/FSETP |src|): abs LOP3 gone
//   - relu folded into accumulate predicate: P2 = (|td|>=0.05) && (raw>0),
//     accumulate raw under @P2 (raw>0 there, so raw == relu value): FMNMX gone
//   - split accumulators across the two prefetch slots (shorter FADD chains)
// Tiling: i-tile 256 (2 rows/thread) x j-tile 128, keep bj>=2*bi; near-diag
// weight 1, far weight 2 (multiplicity-2 proof verified, rel_err 0 since R8).
// ---------------------------------------------------------------------------

#define ARL_TI     256
#define ARL_TJ     128
#define ARL_TB     128
#define ARL_MAXBLK 8192

__device__ float        g_pt[ARL_MAXBLK];
__device__ unsigned int g_pc[ARL_MAXBLK];
__device__ unsigned int g_arr;   // arrival counter (reset by last block)

// one pair; relu folded into the accumulation predicate
__device__ __forceinline__ void arl_pair(float t, float p, float4 v, float mbase,
                                         float& A, float& B, unsigned int& c)
{
    float td = t - v.x;                                     // FADD (fma)
    float pd = p - v.y;                                     // FADD (fma)
    // spd = -sign(td)*pd via sign-bit XOR (1 LOP3, alu)
    float spd = __uint_as_float(__float_as_uint(pd) ^
                                ((~__float_as_uint(td)) & 0x80000000u));
    float cl  = fmaxf(fabsf(td), 0.1f);                     // FMNMX |td| (alu)
    float raw = fmaf(mbase, cl, spd);                       // FFMA (fma)
    bool valid = (fabsf(td) >= 0.05f);                      // FSETP |td| (alu)
    if (valid) c++;                                         // @P1 IADD (alu)
    if (valid && raw > 0.0f) {                              // FSETP.GT.AND (alu)
        A += raw;                                           // @P2 FADD (fma)
        B  = fmaf(v.z, raw, B);                             // @P2 FFMA (fma)
    }
}

__global__ __launch_bounds__(ARL_TB, 8)
void arl_main_kernel(const float* __restrict__ pred,
                     const float* __restrict__ tgt,
                     const float* __restrict__ snr,
                     const int*   __restrict__ msptr,
                     float* __restrict__ out,
                     int n, int nbi, int nbj)
{
    __shared__ float4 tile[ARL_TJ];
    __shared__ float        s_tot[ARL_TB / 32];
    __shared__ unsigned int s_cnt[ARL_TB / 32];
    __shared__ bool         s_last;

    // linear block id -> (bi, bj) over { bj >= 2*bi }
    int b = blockIdx.x;
    int bi = 0;
    while (b >= nbj - 2 * bi) { b -= nbj - 2 * bi; ++bi; }
    const int bj = 2 * bi + b;

    int   iv = *msptr;
    float ms = (iv > -100000 && iv < 100000) ? (float)iv : __int_as_float(iv);
    const float mbase = 0.08f * ms;

    const int c0   = bj * ARL_TJ;
    const int kmax = min(ARL_TJ, n - c0);
    const bool full = ((n & (ARL_TI - 1)) == 0);

    {
        int j = c0 + threadIdx.x;
        if (threadIdx.x < kmax)
            tile[threadIdx.x] = make_float4(tgt[j], pred[j], 0.5f * snr[j], 0.0f);
    }
    __syncthreads();

    const int row0 = bi * ARL_TI + threadIdx.x;
    const int row1 = row0 + ARL_TB;

    // two accumulator sets per row (one per prefetch slot) -> shorter chains
    float A0a = 0.f, A0b = 0.f, B0a = 0.f, B0b = 0.f;
    float A1a = 0.f, A1b = 0.f, B1a = 0.f, B1b = 0.f;
    float h0 = 0.f, h1 = 0.f;
    unsigned int cnt = 0u;

    if (full) {
        const float t0 = tgt[row0], p0 = pred[row0];
        const float t1 = tgt[row1], p1 = pred[row1];
        h0 = 0.5f * snr[row0];  h1 = 0.5f * snr[row1];

        float4 b0 = tile[0], b1 = tile[1];
        #pragma unroll 4
        for (int k = 0; k < ARL_TJ - 2; k += 2) {
            float4 n0 = tile[k + 2];
            float4 n1 = tile[k + 3];
            arl_pair(t0, p0, b0, mbase, A0a, B0a, cnt);
            arl_pair(t1, p1, b0, mbase, A1a, B1a, cnt);
            arl_pair(t0, p0, b1, mbase, A0b, B0b, cnt);
            arl_pair(t1, p1, b1, mbase, A1b, B1b, cnt);
            b0 = n0;  b1 = n1;
        }
        arl_pair(t0, p0, b0, mbase, A0a, B0a, cnt);
        arl_pair(t1, p1, b0, mbase, A1a, B1a, cnt);
        arl_pair(t0, p0, b1, mbase, A0b, B0b, cnt);
        arl_pair(t1, p1, b1, mbase, A1b, B1b, cnt);
    } else {
        if (row0 < n) {
            const float t0 = tgt[row0], p0 = pred[row0];
            h0 = 0.5f * snr[row0];
            for (int k = 0; k < kmax; ++k)
                arl_pair(t0, p0, tile[k], mbase, A0a, B0a, cnt);
        }
        if (row1 < n) {
            const float t1 = tgt[row1], p1 = pred[row1];
            h1 = 0.5f * snr[row1];
            for (int k = 0; k < kmax; ++k)
                arl_pair(t1, p1, tile[k], mbase, A1a, B1a, cnt);
        }
    }

    float A0 = A0a + A0b, B0 = B0a + B0b;
    float A1 = A1a + A1b, B1 = B1a + B1b;
    float total = fmaf(h0, A0, B0) + fmaf(h1, A1, B1);

    #pragma unroll
    for (int o = 16; o; o >>= 1) {
        total += __shfl_xor_sync(0xFFFFFFFFu, total, o);
        cnt   += __shfl_xor_sync(0xFFFFFFFFu, cnt,   o);
    }
    const int wid = threadIdx.x >> 5;
    if ((threadIdx.x & 31) == 0) { s_tot[wid] = total; s_cnt[wid] = cnt; }
    __syncthreads();

    if (threadIdx.x == 0) {
        float        bt = 0.f;
        unsigned int bc = 0u;
        #pragma unroll
        for (int w = 0; w < ARL_TB / 32; ++w) { bt += s_tot[w]; bc += s_cnt[w]; }
        const bool near = ((bj >> 1) == bi);
        g_pt[blockIdx.x] = near ? bt : 2.0f * bt;
        g_pc[blockIdx.x] = near ? bc : 2u * bc;
        __threadfence();
        unsigned int a = atomicAdd(&g_arr, 1u);
        s_last = (a == gridDim.x - 1u);
    }
    __syncthreads();

    if (s_last) {
        const volatile float*        vpt = g_pt;
        const volatile unsigned int* vpc = g_pc;
        float        t = 0.f;
        unsigned int c = 0u;
        for (int i = threadIdx.x; i < (int)gridDim.x; i += ARL_TB) {
            t += vpt[i];
            c += vpc[i];
        }
        #pragma unroll
        for (int o = 16; o; o >>= 1) {
            t += __shfl_xor_sync(0xFFFFFFFFu, t, o);
            c += __shfl_xor_sync(0xFFFFFFFFu, c, o);
        }
        if ((threadIdx.x & 31) == 0) { s_tot[wid] = t; s_cnt[wid] = c; }
        __syncthreads();
        if (threadIdx.x == 0) {
            float        ft = 0.f;
            unsigned int fc = 0u;
            #pragma unroll
            for (int w = 0; w < ARL_TB / 32; ++w) { ft += s_tot[w]; fc += s_cnt[w]; }
            g_arr = 0u;   // reset for next (graph) replay
            out[0] = (fc > 0u) ? (ft / (float)fc) : 0.0f;
        }
    }
}

extern "C" void kernel_launch(void* const* d_in, const int* in_sizes, int n_in,
                              void* d_out, int out_size)
{
    const float* pred = (const float*)d_in[0];
    const float* tgt  = (const float*)d_in[1];
    const float* snr  = (const float*)d_in[2];
    const int*   ms   = (const int*)  d_in[3];
    float*       out  = (float*)d_out;
    const int n   = in_sizes[0];
    const int nbi = (n + ARL_TI - 1) / ARL_TI;
    const int nbj = (n + ARL_TJ - 1) / ARL_TJ;

    int nblk = 0;
    for (int bi = 0; bi < nbi; ++bi) {
        int c = nbj - 2 * bi;
        if (c > 0) nblk += c;
    }

    arl_main_kernel<<<nblk, ARL_TB>>>(pred, tgt, snr, ms, out, n, nbi, nbj);
}

// round 12
// speedup vs baseline: 1.2754x; 1.2754x over previous
#include <cuda_runtime.h>
#include <cuda_bf16.h>

// ---------------------------------------------------------------------------
// AdaptiveRankingLoss R12: R10 skeleton + abs-operand-modifiers + 3 rows/thread
// + NaN edge padding.
//   loss = mean over valid pairs (|t_i-t_j| >= 0.05, i<j) of
//          0.5*(s_i+s_j)*relu(-sign(t_i-t_j)*(p_i-p_j) + 0.08*ms*clip(ad,0.1,1))
// Tiling: i-tile 384 (TB=128, 3 rows/thread) x j-tile 128; keep bj >= 3*bi.
// Near blocks (bj-3bi <= 2): j-range inside i-range -> both pair orders -> w=1;
// far blocks w=2. Every unordered pair contributes exactly 2 weighted ordered
// evals (R8 proof generalized). Dead rows / tile slots use t=NaN: FSETP.GE is
// false on NaN -> zero contribution to sum AND count -> single uniform path.
// Single-predicate if{} (R7/R11 both proved alternatives regress). Last CTA
// reduces per-block partials in-kernel.
// ---------------------------------------------------------------------------

#define ARL_TI     384           // i-tile (3 rows per thread)
#define ARL_TJ     128           // j-tile
#define ARL_TB     128           // threads per CTA
#define ARL_MAXBLK 8192

__device__ float        g_pt[ARL_MAXBLK];
__device__ unsigned int g_pc[ARL_MAXBLK];
__device__ unsigned int g_arr;   // arrival counter (reset by last block)

// one pair; abs consumed as |src| operand modifier; single predicate -> @P
__device__ __forceinline__ void arl_pair(float t, float p, float4 v, float mbase,
                                         float& A, float& B, unsigned int& c)
{
    float td  = t - v.x;                                    // FADD (fma)
    float pd  = p - v.y;                                    // FADD (fma)
    // spd = -sign(td)*pd : one LOP3 (alu)
    float spd = __uint_as_float(__float_as_uint(pd) ^
                                ((~__float_as_uint(td)) & 0x80000000u));
    float cl  = fmaxf(fabsf(td), 0.1f);                     // FMNMX |td| (alu)
    float vio = fmaxf(fmaf(mbase, cl, spd), 0.0f);          // FFMA (fma) + FMNMX (alu)
    if (fabsf(td) >= 0.05f) {                               // FSETP |td| (alu); NaN -> false
        A += vio;                                           // @P FADD (fma)
        B  = fmaf(v.z, vio, B);                             // @P FFMA (fma)
        c++;                                                // @P IADD (alu)
    }
}

__global__ __launch_bounds__(ARL_TB, 8)
void arl_main_kernel(const float* __restrict__ pred,
                     const float* __restrict__ tgt,
                     const float* __restrict__ snr,
                     const int*   __restrict__ msptr,
                     float* __restrict__ out,
                     int n, int nbi, int nbj)
{
    __shared__ float4 tile[ARL_TJ];
    __shared__ float        s_tot[ARL_TB / 32];
    __shared__ unsigned int s_cnt[ARL_TB / 32];
    __shared__ bool         s_last;

    // linear block id -> (bi, bj) over { bj >= 3*bi }
    int b = blockIdx.x;
    int bi = 0;
    while (b >= nbj - 3 * bi) { b -= nbj - 3 * bi; ++bi; }
    const int bj = 3 * bi + b;

    int   iv = *msptr;
    float ms = (iv > -100000 && iv < 100000) ? (float)iv : __int_as_float(iv);
    const float mbase = 0.08f * ms;

    const float NaN = __uint_as_float(0x7FC00000u);

    // stage j-tile; dead slots get t=NaN (contribute nothing)
    {
        int j = bj * ARL_TJ + threadIdx.x;
        if (j < n) tile[threadIdx.x] = make_float4(tgt[j], pred[j], 0.5f * snr[j], 0.0f);
        else       tile[threadIdx.x] = make_float4(NaN, 0.0f, 0.0f, 0.0f);
    }
    __syncthreads();

    const int row0 = bi * ARL_TI + threadIdx.x;   // always < n for selected blocks
    const int row1 = row0 + ARL_TB;
    const int row2 = row1 + ARL_TB;

    // dead rows -> t = NaN (predicate never fires)
    const float t0 = (row0 < n) ? tgt[row0]  : NaN;
    const float p0 = (row0 < n) ? pred[row0] : 0.0f;
    const float h0 = (row0 < n) ? 0.5f * snr[row0] : 0.0f;
    const float t1 = (row1 < n) ? tgt[row1]  : NaN;
    const float p1 = (row1 < n) ? pred[row1] : 0.0f;
    const float h1 = (row1 < n) ? 0.5f * snr[row1] : 0.0f;
    const float t2 = (row2 < n) ? tgt[row2]  : NaN;
    const float p2 = (row2 < n) ? pred[row2] : 0.0f;
    const float h2 = (row2 < n) ? 0.5f * snr[row2] : 0.0f;

    float A0 = 0.f, B0 = 0.f, A1 = 0.f, B1 = 0.f, A2 = 0.f, B2 = 0.f;
    unsigned int cnt = 0u;

    // distance-2 prefetch; 6 pair-evals per 2-column step
    {
        float4 b0 = tile[0], b1 = tile[1];
        #pragma unroll 2
        for (int k = 0; k < ARL_TJ - 2; k += 2) {
            float4 n0 = tile[k + 2];
            float4 n1 = tile[k + 3];
            arl_pair(t0, p0, b0, mbase, A0, B0, cnt);
            arl_pair(t1, p1, b0, mbase, A1, B1, cnt);
            arl_pair(t2, p2, b0, mbase, A2, B2, cnt);
            arl_pair(t0, p0, b1, mbase, A0, B0, cnt);
            arl_pair(t1, p1, b1, mbase, A1, B1, cnt);
            arl_pair(t2, p2, b1, mbase, A2, B2, cnt);
            b0 = n0;  b1 = n1;
        }
        arl_pair(t0, p0, b0, mbase, A0, B0, cnt);
        arl_pair(t1, p1, b0, mbase, A1, B1, cnt);
        arl_pair(t2, p2, b0, mbase, A2, B2, cnt);
        arl_pair(t0, p0, b1, mbase, A0, B0, cnt);
        arl_pair(t1, p1, b1, mbase, A1, B1, cnt);
        arl_pair(t2, p2, b1, mbase, A2, B2, cnt);
    }

    float total = fmaf(h0, A0, B0) + fmaf(h1, A1, B1) + fmaf(h2, A2, B2);

    #pragma unroll
    for (int o = 16; o; o >>= 1) {
        total += __shfl_xor_sync(0xFFFFFFFFu, total, o);
        cnt   += __shfl_xor_sync(0xFFFFFFFFu, cnt,   o);
    }
    const int wid = threadIdx.x >> 5;
    if ((threadIdx.x & 31) == 0) { s_tot[wid] = total; s_cnt[wid] = cnt; }
    __syncthreads();

    if (threadIdx.x == 0) {
        float        bt = 0.f;
        unsigned int bc = 0u;
        #pragma unroll
        for (int w = 0; w < ARL_TB / 32; ++w) { bt += s_tot[w]; bc += s_cnt[w]; }
        const bool near = ((bj - 3 * bi) <= 2);   // j-range inside i-range
        g_pt[blockIdx.x] = near ? bt : 2.0f * bt;
        g_pc[blockIdx.x] = near ? bc : 2u * bc;
        __threadfence();
        unsigned int a = atomicAdd(&g_arr, 1u);
        s_last = (a == gridDim.x - 1u);
    }
    __syncthreads();

    if (s_last) {
        const volatile float*        vpt = g_pt;
        const volatile unsigned int* vpc = g_pc;
        float        t = 0.f;
        unsigned int c = 0u;
        for (int i = threadIdx.x; i < (int)gridDim.x; i += ARL_TB) {
            t += vpt[i];
            c += vpc[i];
        }
        #pragma unroll
        for (int o = 16; o; o >>= 1) {
            t += __shfl_xor_sync(0xFFFFFFFFu, t, o);
            c += __shfl_xor_sync(0xFFFFFFFFu, c, o);
        }
        if ((threadIdx.x & 31) == 0) { s_tot[wid] = t; s_cnt[wid] = c; }
        __syncthreads();
        if (threadIdx.x == 0) {
            float        ft = 0.f;
            unsigned int fc = 0u;
            #pragma unroll
            for (int w = 0; w < ARL_TB / 32; ++w) { ft += s_tot[w]; fc += s_cnt[w]; }
            g_arr = 0u;   // reset for next (graph) replay
            out[0] = (fc > 0u) ? (ft / (float)fc) : 0.0f;
        }
    }
}

extern "C" void kernel_launch(void* const* d_in, const int* in_sizes, int n_in,
                              void* d_out, int out_size)
{
    const float* pred = (const float*)d_in[0];
    const float* tgt  = (const float*)d_in[1];
    const float* snr  = (const float*)d_in[2];
    const int*   ms   = (const int*)  d_in[3];
    float*       out  = (float*)d_out;
    const int n   = in_sizes[0];
    const int nbi = (n + ARL_TI - 1) / ARL_TI;
    const int nbj = (n + ARL_TJ - 1) / ARL_TJ;

    int nblk = 0;
    for (int bi = 0; bi < nbi; ++bi) {
        int c = nbj - 3 * bi;
        if (c > 0) nblk += c;
    }

    arl_main_kernel<<<nblk, ARL_TB>>>(pred, tgt, snr, ms, out, n, nbi, nbj);
}

// round 13
// speedup vs baseline: 1.2809x; 1.0043x over previous
#include <cuda_runtime.h>
#include <cuda_bf16.h>

// ---------------------------------------------------------------------------
// AdaptiveRankingLoss R13: R12 skeleton + packed f32x2 differences +
// 4 rows/thread.
//   loss = mean over valid pairs (|t_i-t_j| >= 0.05, i<j) of
//          0.5*(s_i+s_j)*relu(-sign(t_i-t_j)*(p_i-p_j) + 0.08*ms*clip(ad,0.1,1))
// Tiling: i-tile 512 (TB=128, 4 rows/thread) x j-tile 128; keep bj >= 4*bi.
// Near blocks (bj-4bi <= 3) weight 1 (both pair orders appear across the near
// blocks of the same i-tile); far blocks weight 2 (one order). Every unordered
// pair -> exactly 2 weighted ordered evals (proof in R8/R12 lineage).
// Tile stores NEGATED (t,p) so one add.rn.f32x2 produces (td,pd) — FADD2
// replaces two FADDs (ptxas only emits it via explicit PTX). NaN padding for
// dead rows/cols keeps a single uniform predicated path. Last CTA reduces.
// ---------------------------------------------------------------------------

#define ARL_TI     512           // i-tile (4 rows per thread)
#define ARL_TJ     128           // j-tile
#define ARL_TB     128           // threads per CTA
#define ARL_MAXBLK 8192

__device__ float        g_pt[ARL_MAXBLK];
__device__ unsigned int g_pc[ARL_MAXBLK];
__device__ unsigned int g_arr;   // arrival counter (reset by last block)

__device__ __forceinline__ unsigned long long arl_pack2(float lo, float hi)
{
    unsigned long long r;
    asm("mov.b64 %0, {%1, %2};" : "=l"(r) : "f"(lo), "f"(hi));
    return r;
}

// one pair; tp = packed (t_i, p_i); v = (-t_j, -p_j, h_j, _)
__device__ __forceinline__ void arl_pair(unsigned long long tp, float4 v, float mbase,
                                         float& A, float& B, unsigned int& c)
{
    unsigned long long nv = arl_pack2(v.x, v.y);            // reg-pair naming (free)
    unsigned long long d;
    asm("add.rn.f32x2 %0, %1, %2;" : "=l"(d) : "l"(tp), "l"(nv));  // FADD2: (td,pd)
    float td, pd;
    asm("mov.b64 {%0, %1}, %2;" : "=f"(td), "=f"(pd) : "l"(d));
    // spd = -sign(td)*pd : one LOP3 (alu)
    float spd = __uint_as_float(__float_as_uint(pd) ^
                                ((~__float_as_uint(td)) & 0x80000000u));
    float cl  = fmaxf(fabsf(td), 0.1f);                     // FMNMX |td|
    float vio = fmaxf(fmaf(mbase, cl, spd), 0.0f);          // FFMA + FMNMX
    if (fabsf(td) >= 0.05f) {                               // FSETP |td|; NaN -> false
        A += vio;                                           // @P FADD
        B  = fmaf(v.z, vio, B);                             // @P FFMA
        c++;                                                // @P IADD
    }
}

__global__ __launch_bounds__(ARL_TB, 4)
void arl_main_kernel(const float* __restrict__ pred,
                     const float* __restrict__ tgt,
                     const float* __restrict__ snr,
                     const int*   __restrict__ msptr,
                     float* __restrict__ out,
                     int n, int nbi, int nbj)
{
    __shared__ float4 tile[ARL_TJ];
    __shared__ float        s_tot[ARL_TB / 32];
    __shared__ unsigned int s_cnt[ARL_TB / 32];
    __shared__ bool         s_last;

    // linear block id -> (bi, bj) over { bj >= 4*bi }
    int b = blockIdx.x;
    int bi = 0;
    while (b >= nbj - 4 * bi) { b -= nbj - 4 * bi; ++bi; }
    const int bj = 4 * bi + b;

    int   iv = *msptr;
    float ms = (iv > -100000 && iv < 100000) ? (float)iv : __int_as_float(iv);
    const float mbase = 0.08f * ms;

    const float NaN = __uint_as_float(0x7FC00000u);

    // stage NEGATED j-tile; dead slots get NaN (contribute nothing)
    {
        int j = bj * ARL_TJ + threadIdx.x;
        if (j < n) tile[threadIdx.x] = make_float4(-tgt[j], -pred[j], 0.5f * snr[j], 0.0f);
        else       tile[threadIdx.x] = make_float4(NaN, 0.0f, 0.0f, 0.0f);
    }
    __syncthreads();

    const int row0 = bi * ARL_TI + threadIdx.x;
    const int row1 = row0 + ARL_TB;
    const int row2 = row1 + ARL_TB;
    const int row3 = row2 + ARL_TB;

    const unsigned long long tp0 = arl_pack2((row0 < n) ? tgt[row0] : NaN,
                                             (row0 < n) ? pred[row0] : 0.0f);
    const unsigned long long tp1 = arl_pack2((row1 < n) ? tgt[row1] : NaN,
                                             (row1 < n) ? pred[row1] : 0.0f);
    const unsigned long long tp2 = arl_pack2((row2 < n) ? tgt[row2] : NaN,
                                             (row2 < n) ? pred[row2] : 0.0f);
    const unsigned long long tp3 = arl_pack2((row3 < n) ? tgt[row3] : NaN,
                                             (row3 < n) ? pred[row3] : 0.0f);
    const float h0 = (row0 < n) ? 0.5f * snr[row0] : 0.0f;
    const float h1 = (row1 < n) ? 0.5f * snr[row1] : 0.0f;
    const float h2 = (row2 < n) ? 0.5f * snr[row2] : 0.0f;
    const float h3 = (row3 < n) ? 0.5f * snr[row3] : 0.0f;

    float A0 = 0.f, B0 = 0.f, A1 = 0.f, B1 = 0.f;
    float A2 = 0.f, B2 = 0.f, A3 = 0.f, B3 = 0.f;
    unsigned int cnt = 0u;

    // distance-2 prefetch; 8 pair-evals per 2-column step
    {
        float4 b0 = tile[0], b1 = tile[1];
        #pragma unroll 2
        for (int k = 0; k < ARL_TJ - 2; k += 2) {
            float4 n0 = tile[k + 2];
            float4 n1 = tile[k + 3];
            arl_pair(tp0, b0, mbase, A0, B0, cnt);
            arl_pair(tp1, b0, mbase, A1, B1, cnt);
            arl_pair(tp2, b0, mbase, A2, B2, cnt);
            arl_pair(tp3, b0, mbase, A3, B3, cnt);
            arl_pair(tp0, b1, mbase, A0, B0, cnt);
            arl_pair(tp1, b1, mbase, A1, B1, cnt);
            arl_pair(tp2, b1, mbase, A2, B2, cnt);
            arl_pair(tp3, b1, mbase, A3, B3, cnt);
            b0 = n0;  b1 = n1;
        }
        arl_pair(tp0, b0, mbase, A0, B0, cnt);
        arl_pair(tp1, b0, mbase, A1, B1, cnt);
        arl_pair(tp2, b0, mbase, A2, B2, cnt);
        arl_pair(tp3, b0, mbase, A3, B3, cnt);
        arl_pair(tp0, b1, mbase, A0, B0, cnt);
        arl_pair(tp1, b1, mbase, A1, B1, cnt);
        arl_pair(tp2, b1, mbase, A2, B2, cnt);
        arl_pair(tp3, b1, mbase, A3, B3, cnt);
    }

    float total = fmaf(h0, A0, B0) + fmaf(h1, A1, B1)
                + fmaf(h2, A2, B2) + fmaf(h3, A3, B3);

    #pragma unroll
    for (int o = 16; o; o >>= 1) {
        total += __shfl_xor_sync(0xFFFFFFFFu, total, o);
        cnt   += __shfl_xor_sync(0xFFFFFFFFu, cnt,   o);
    }
    const int wid = threadIdx.x >> 5;
    if ((threadIdx.x & 31) == 0) { s_tot[wid] = total; s_cnt[wid] = cnt; }
    __syncthreads();

    if (threadIdx.x == 0) {
        float        bt = 0.f;
        unsigned int bc = 0u;
        #pragma unroll
        for (int w = 0; w < ARL_TB / 32; ++w) { bt += s_tot[w]; bc += s_cnt[w]; }
        const bool near = ((bj - 4 * bi) <= 3);   // j-range inside i-range
        g_pt[blockIdx.x] = near ? bt : 2.0f * bt;
        g_pc[blockIdx.x] = near ? bc : 2u * bc;
        __threadfence();
        unsigned int a = atomicAdd(&g_arr, 1u);
        s_last = (a == gridDim.x - 1u);
    }
    __syncthreads();

    if (s_last) {
        const volatile float*        vpt = g_pt;
        const volatile unsigned int* vpc = g_pc;
        float        t = 0.f;
        unsigned int c = 0u;
        for (int i = threadIdx.x; i < (int)gridDim.x; i += ARL_TB) {
            t += vpt[i];
            c += vpc[i];
        }
        #pragma unroll
        for (int o = 16; o; o >>= 1) {
            t += __shfl_xor_sync(0xFFFFFFFFu, t, o);
            c += __shfl_xor_sync(0xFFFFFFFFu, c, o);
        }
        if ((threadIdx.x & 31) == 0) { s_tot[wid] = t; s_cnt[wid] = c; }
        __syncthreads();
        if (threadIdx.x == 0) {
            float        ft = 0.f;
            unsigned int fc = 0u;
            #pragma unroll
            for (int w = 0; w < ARL_TB / 32; ++w) { ft += s_tot[w]; fc += s_cnt[w]; }
            g_arr = 0u;   // reset for next (graph) replay
            out[0] = (fc > 0u) ? (ft / (float)fc) : 0.0f;
        }
    }
}

extern "C" void kernel_launch(void* const* d_in, const int* in_sizes, int n_in,
                              void* d_out, int out_size)
{
    const float* pred = (const float*)d_in[0];
    const float* tgt  = (const float*)d_in[1];
    const float* snr  = (const float*)d_in[2];
    const int*   ms   = (const int*)  d_in[3];
    float*       out  = (float*)d_out;
    const int n   = in_sizes[0];
    const int nbi = (n + ARL_TI - 1) / ARL_TI;
    const int nbj = (n + ARL_TJ - 1) / ARL_TJ;

    int nblk = 0;
    for (int bi = 0; bi < nbi; ++bi) {
        int c = nbj - 4 * bi;
        if (c > 0) nblk += c;
    }

    arl_main_kernel<<<nblk, ARL_TB>>>(pred, tgt, snr, ms, out, n, nbi, nbj);
}